// round 2
// baseline (speedup 1.0000x reference)
#include <cuda_runtime.h>
#include <math_constants.h>

#define SS 4096
#define II 1024
#define CC 8
#define HH 8
#define SBLK (SS/32)   // 128 s-blocks for K1 partials

// ---- scratch (device globals; no runtime allocation) ----
__device__ float g_k[(size_t)II*SS];          // k  [i][s]
__device__ float g_v[(size_t)II*SS];          // v  [i][s]
__device__ float g_b[(size_t)II*SS];          // bias [i][s]
__device__ float g_qpart[(size_t)SBLK*II*9];  // per-(sblk,i): qsum[8], masksum
__device__ float g_o[(size_t)II*HH];          // attention output per column

// ============================================================
// K1: LayerNorm + k/v/bias (transposed write) + q-pool partials
// grid (II/32, SS/32), block 256  (lane=i_local, warp covers 4 s)
// ============================================================
__global__ __launch_bounds__(256) void k1_kernel(
    const float* __restrict__ m, const float* __restrict__ mask,
    const float* __restrict__ gamma, const float* __restrict__ beta,
    const float* __restrict__ Wk, const float* __restrict__ Wv)
{
    __shared__ float tk[32][33], tv[32][33], tb[32][33];
    __shared__ float red[3][8][33];
    __shared__ float wgt[32];
    int tid = threadIdx.x;
    if (tid < 32) {
        float v;
        if      (tid <  8) v = gamma[tid];
        else if (tid < 16) v = beta[tid-8];
        else if (tid < 24) v = Wk[tid-16];
        else               v = Wv[tid-24];
        wgt[tid] = v;
    }
    __syncthreads();

    int il = tid & 31, wp = tid >> 5;
    int i  = blockIdx.x*32 + il;
    int s0 = blockIdx.y*32;

    float qacc[8];
    #pragma unroll
    for (int c = 0; c < 8; c++) qacc[c] = 0.f;
    float macc = 0.f;

    #pragma unroll
    for (int ssl = 0; ssl < 4; ssl++) {
        int sl = wp*4 + ssl;
        int s  = s0 + sl;
        const float4* p = reinterpret_cast<const float4*>(m + ((size_t)s*II + i)*CC);
        float4 a = p[0], b4 = p[1];
        float x[8] = {a.x,a.y,a.z,a.w,b4.x,b4.y,b4.z,b4.w};
        float mu = 0.f;
        #pragma unroll
        for (int c = 0; c < 8; c++) mu += x[c];
        mu *= 0.125f;
        float var = 0.f;
        #pragma unroll
        for (int c = 0; c < 8; c++) { float d = x[c]-mu; var += d*d; }
        var *= 0.125f;
        float rstd = rsqrtf(var + 1e-5f);
        float mk = mask[(size_t)s*II + i];
        float kv = 0.f, vv = 0.f;
        #pragma unroll
        for (int c = 0; c < 8; c++) {
            float mn = (x[c]-mu)*rstd*wgt[c] + wgt[8+c];
            kv += mn*wgt[16+c];
            vv += mn*wgt[24+c];
            qacc[c] += mn*mk;
        }
        macc += mk;
        tk[il][sl] = kv;
        tv[il][sl] = vv;
        tb[il][sl] = 1e9f*(mk - 1.f);
    }
    __syncthreads();

    // coalesced transposed plane writeout: thread -> (i-row, 4 consecutive s)
    {
        int ir = tid >> 3, sj = (tid & 7)*4;
        size_t off = (size_t)(blockIdx.x*32 + ir)*SS + s0 + sj;
        *reinterpret_cast<float4*>(g_k + off) =
            make_float4(tk[ir][sj], tk[ir][sj+1], tk[ir][sj+2], tk[ir][sj+3]);
        *reinterpret_cast<float4*>(g_v + off) =
            make_float4(tv[ir][sj], tv[ir][sj+1], tv[ir][sj+2], tv[ir][sj+3]);
        *reinterpret_cast<float4*>(g_b + off) =
            make_float4(tb[ir][sj], tb[ir][sj+1], tb[ir][sj+2], tb[ir][sj+3]);
    }

    // q-pool partials: 9 channels reduced over the 8 warps, 3 at a time
    #pragma unroll
    for (int r = 0; r < 3; r++) {
        __syncthreads();
        #pragma unroll
        for (int gch = 0; gch < 3; gch++) {
            int c = r*3 + gch;
            red[gch][wp][il] = (c < 8) ? qacc[c] : macc;
        }
        __syncthreads();
        if (wp < 3) {
            int c = r*3 + wp;
            float sum = 0.f;
            #pragma unroll
            for (int w = 0; w < 8; w++) sum += red[wp][w][il];
            g_qpart[((size_t)blockIdx.y*II + i)*9 + c] = sum;
        }
    }
}

// ---------------- block reduction helpers ----------------
__device__ __forceinline__ float warp_sum(float v) {
    #pragma unroll
    for (int o = 16; o; o >>= 1) v += __shfl_xor_sync(0xffffffffu, v, o);
    return v;
}
__device__ __forceinline__ float warp_max(float v) {
    #pragma unroll
    for (int o = 16; o; o >>= 1) v = fmaxf(v, __shfl_xor_sync(0xffffffffu, v, o));
    return v;
}
template<int N, bool DOMAX>
__device__ __forceinline__ void block_reduce(float* vals, float* buf, int nwarps) {
    int lane = threadIdx.x & 31, wp = threadIdx.x >> 5;
    __syncthreads();
    #pragma unroll
    for (int n = 0; n < N; n++) {
        float v = DOMAX ? warp_max(vals[n]) : warp_sum(vals[n]);
        if (lane == 0) buf[wp*N + n] = v;
    }
    __syncthreads();
    if (threadIdx.x < N) {
        float r = buf[threadIdx.x];
        for (int w = 1; w < nwarps; w++) {
            float t = buf[w*N + threadIdx.x];
            r = DOMAX ? fmaxf(r, t) : (r + t);
        }
        buf[nwarps*N + threadIdx.x] = r;
    }
    __syncthreads();
    #pragma unroll
    for (int n = 0; n < N; n++) vals[n] = buf[nwarps*N + n];
}

// ============================================================
// K2: per-column q + rank-1 softmax over s -> o[i][h]
// grid 1024, block 256 (16 s per thread)
// ============================================================
__global__ __launch_bounds__(256) void k2_kernel(const float* __restrict__ Wq)
{
    __shared__ float buf[(8+1)*16];
    __shared__ float swq[64];
    int tid = threadIdx.x;
    int i = blockIdx.x;
    if (tid < 64) swq[tid] = Wq[tid];

    float part[9];
    #pragma unroll
    for (int c = 0; c < 9; c++) part[c] = 0.f;
    if (tid < SBLK) {
        const float* p = g_qpart + ((size_t)tid*II + i)*9;
        #pragma unroll
        for (int c = 0; c < 9; c++) part[c] = p[c];
    }
    block_reduce<9,false>(part, buf, 8);

    float inv = 1.f/(part[8] + 1e-5f);
    float q[8];
    #pragma unroll
    for (int h = 0; h < 8; h++) {
        float s = 0.f;
        #pragma unroll
        for (int c = 0; c < 8; c++) s += (part[c]*inv)*swq[c*8 + h];
        q[h] = s;   // * c_h^-0.5 == 1 (c_h = 1)
    }

    float kk[16], vv[16], bb[16];
    const float* kp = g_k + (size_t)i*SS;
    const float* vp = g_v + (size_t)i*SS;
    const float* bp = g_b + (size_t)i*SS;
    #pragma unroll
    for (int t = 0; t < 16; t++) {
        int s = tid + t*256;
        kk[t] = kp[s]; vv[t] = vp[s]; bb[t] = bp[s];
    }

    float hm[8];
    #pragma unroll
    for (int h = 0; h < 8; h++) hm[h] = -CUDART_INF_F;
    #pragma unroll
    for (int t = 0; t < 16; t++)
        #pragma unroll
        for (int h = 0; h < 8; h++)
            hm[h] = fmaxf(hm[h], q[h]*kk[t] + bb[t]);
    block_reduce<8,true>(hm, buf, 8);

    float so[16];
    #pragma unroll
    for (int n = 0; n < 16; n++) so[n] = 0.f;
    #pragma unroll
    for (int t = 0; t < 16; t++) {
        #pragma unroll
        for (int h = 0; h < 8; h++) {
            float e = __expf(q[h]*kk[t] + bb[t] - hm[h]);
            so[h]   += e;
            so[8+h] += e*vv[t];
        }
    }
    block_reduce<16,false>(so, buf, 8);

    if (tid < 8) g_o[(size_t)i*8 + tid] = so[8+tid] / so[tid];
}

// ============================================================
// K3: re-read m, recompute LN, gate + output projection
// grid (II/32, SS/16), block 256; each thread does 2 s-positions
// ============================================================
__global__ __launch_bounds__(256) void k3_kernel(
    const float* __restrict__ m,
    const float* __restrict__ gamma, const float* __restrict__ beta,
    const float* __restrict__ Wg, const float* __restrict__ bg,
    const float* __restrict__ Wo, const float* __restrict__ bo,
    float* __restrict__ out)
{
    __shared__ float sw[160]; // Wg[0:64] Wo[64:128] bg[128:136] bo[136:144] gamma[144:152] beta[152:160]
    int tid = threadIdx.x;
    if (tid < 160) {
        float v;
        if      (tid <  64) v = Wg[tid];
        else if (tid < 128) v = Wo[tid-64];
        else if (tid < 136) v = bg[tid-128];
        else if (tid < 144) v = bo[tid-136];
        else if (tid < 152) v = gamma[tid-144];
        else                v = beta[tid-152];
        sw[tid] = v;
    }
    int il = tid & 31, wp = tid >> 5;
    int i  = blockIdx.x*32 + il;
    int s1 = blockIdx.y*16 + wp;   // and s1+8

    float o[8];
    {
        const float4* po = reinterpret_cast<const float4*>(g_o + (size_t)i*8);
        float4 a = po[0], b4 = po[1];
        o[0]=a.x; o[1]=a.y; o[2]=a.z; o[3]=a.w;
        o[4]=b4.x; o[5]=b4.y; o[6]=b4.z; o[7]=b4.w;
    }
    __syncthreads();

    float x1[8], x2[8];
    {
        const float4* p = reinterpret_cast<const float4*>(m + ((size_t)s1*II + i)*CC);
        float4 a = p[0], b4 = p[1];
        x1[0]=a.x; x1[1]=a.y; x1[2]=a.z; x1[3]=a.w;
        x1[4]=b4.x; x1[5]=b4.y; x1[6]=b4.z; x1[7]=b4.w;
    }
    {
        const float4* p = reinterpret_cast<const float4*>(m + ((size_t)(s1+8)*II + i)*CC);
        float4 a = p[0], b4 = p[1];
        x2[0]=a.x; x2[1]=a.y; x2[2]=a.z; x2[3]=a.w;
        x2[4]=b4.x; x2[5]=b4.y; x2[6]=b4.z; x2[7]=b4.w;
    }

    // LayerNorm both rows in-place
    #pragma unroll
    for (int r = 0; r < 2; r++) {
        float* x = r ? x2 : x1;
        float mu = 0.f;
        #pragma unroll
        for (int c = 0; c < 8; c++) mu += x[c];
        mu *= 0.125f;
        float var = 0.f;
        #pragma unroll
        for (int c = 0; c < 8; c++) { float d = x[c]-mu; var += d*d; }
        var *= 0.125f;
        float rstd = rsqrtf(var + 1e-5f);
        #pragma unroll
        for (int c = 0; c < 8; c++) x[c] = (x[c]-mu)*rstd*sw[144+c] + sw[152+c];
    }

    float a1[8], a2[8];
    #pragma unroll
    for (int c = 0; c < 8; c++) { a1[c] = 0.f; a2[c] = 0.f; }

    #pragma unroll
    for (int h = 0; h < 8; h++) {
        float z1 = sw[128+h], z2 = z1;
        #pragma unroll
        for (int c = 0; c < 8; c++) {
            float w = sw[c*8 + h];
            z1 += x1[c]*w; z2 += x2[c]*w;
        }
        float t1 = o[h] * __fdividef(1.f, 1.f + __expf(-z1));
        float t2 = o[h] * __fdividef(1.f, 1.f + __expf(-z2));
        #pragma unroll
        for (int c = 0; c < 8; c++) {
            float w = sw[64 + h*8 + c];
            a1[c] += t1*w; a2[c] += t2*w;
        }
    }

    {
        size_t off = ((size_t)s1*II + i)*CC;
        *reinterpret_cast<float4*>(out + off) =
            make_float4(a1[0]+sw[136], a1[1]+sw[137], a1[2]+sw[138], a1[3]+sw[139]);
        *reinterpret_cast<float4*>(out + off + 4) =
            make_float4(a1[4]+sw[140], a1[5]+sw[141], a1[6]+sw[142], a1[7]+sw[143]);
    }
    {
        size_t off = ((size_t)(s1+8)*II + i)*CC;
        *reinterpret_cast<float4*>(out + off) =
            make_float4(a2[0]+sw[136], a2[1]+sw[137], a2[2]+sw[138], a2[3]+sw[139]);
        *reinterpret_cast<float4*>(out + off + 4) =
            make_float4(a2[4]+sw[140], a2[5]+sw[141], a2[6]+sw[142], a2[7]+sw[143]);
    }
}

// ============================================================
extern "C" void kernel_launch(void* const* d_in, const int* in_sizes, int n_in,
                              void* d_out, int out_size)
{
    const float* m     = (const float*)d_in[0];
    const float* mask  = (const float*)d_in[1];
    const float* gamma = (const float*)d_in[2];
    const float* beta  = (const float*)d_in[3];
    const float* Wq    = (const float*)d_in[4];
    const float* Wk    = (const float*)d_in[5];
    const float* Wv    = (const float*)d_in[6];
    const float* Wg    = (const float*)d_in[7];
    const float* bg    = (const float*)d_in[8];
    const float* Wo    = (const float*)d_in[9];
    const float* bo    = (const float*)d_in[10];
    float* out = (float*)d_out;

    dim3 g1(II/32, SS/32);
    k1_kernel<<<g1, 256>>>(m, mask, gamma, beta, Wk, Wv);
    k2_kernel<<<II, 256>>>(Wq);
    dim3 g3(II/32, SS/16);
    k3_kernel<<<g3, 256>>>(m, gamma, beta, Wg, bg, Wo, bo, out);
}